// round 11
// baseline (speedup 1.0000x reference)
#include <cuda_runtime.h>
#include <cuda_bf16.h>
#include <cstdint>
#include <math.h>

#define BB   2
#define SS   2048
#define DD   1024
#define HH   8
#define EE   4
#define DHH  128
#define TOK  (BB*SS)
#define SCALE 0.29730177875068026f      /* 128^-0.25 */

/* ------------------------------------------------------------------ */
/* scratch (device globals)                                            */
/* ------------------------------------------------------------------ */
__device__ float g_res[TOK * DD];      /* [t, h*128+dh] */
__device__ float g_gv[TOK * HH * EE];
__device__ float g_go[TOK * HH * EE];

/* pre-split activations: [b,h,s,dh] layout */
__device__ __nv_bfloat16 g_qh[TOK * DD], g_ql[TOK * DD];
__device__ __nv_bfloat16 g_kh[TOK * DD], g_kl[TOK * DD];
__device__ __nv_bfloat16 g_vh[TOK * DD], g_vl[TOK * DD];

/* pre-split weights */
__device__ __nv_bfloat16 g_wqh[DD * DD], g_wql[DD * DD];
__device__ __nv_bfloat16 g_wkh[DD * DD], g_wkl[DD * DD];
__device__ __nv_bfloat16 g_wvh[HH * EE * DD * DHH], g_wvl[HH * EE * DD * DHH];
__device__ __nv_bfloat16 g_woh[HH * EE * DHH * DD], g_wol[HH * EE * DHH * DD];

/* ------------------------------------------------------------------ */
/* helpers                                                             */
/* ------------------------------------------------------------------ */
__device__ __forceinline__ uint32_t smem_u32(const void* p) {
    return (uint32_t)__cvta_generic_to_shared(p);
}
__device__ __forceinline__ void ldsm4(uint32_t* r, uint32_t a) {
    asm volatile("ldmatrix.sync.aligned.m8n8.x4.shared.b16 {%0,%1,%2,%3}, [%4];"
                 : "=r"(r[0]), "=r"(r[1]), "=r"(r[2]), "=r"(r[3]) : "r"(a));
}
__device__ __forceinline__ void ldsm4t(uint32_t* r, uint32_t a) {
    asm volatile("ldmatrix.sync.aligned.m8n8.x4.trans.shared.b16 {%0,%1,%2,%3}, [%4];"
                 : "=r"(r[0]), "=r"(r[1]), "=r"(r[2]), "=r"(r[3]) : "r"(a));
}
__device__ __forceinline__ void mma16816(float* d, const uint32_t* a, const uint32_t* b) {
    asm volatile(
        "mma.sync.aligned.m16n8k16.row.col.f32.bf16.bf16.f32 "
        "{%0,%1,%2,%3}, {%4,%5,%6,%7}, {%8,%9}, {%0,%1,%2,%3};"
        : "+f"(d[0]), "+f"(d[1]), "+f"(d[2]), "+f"(d[3])
        : "r"(a[0]), "r"(a[1]), "r"(a[2]), "r"(a[3]), "r"(b[0]), "r"(b[1]));
}
__device__ __forceinline__ uint32_t packbf(float x, float y) {
    __nv_bfloat162 t = __floats2bfloat162_rn(x, y);
    return *reinterpret_cast<uint32_t*>(&t);
}
__device__ __forceinline__ void split_pair(float x, float y, uint32_t& h, uint32_t& l) {
    float hx = __bfloat162float(__float2bfloat16(x));
    float hy = __bfloat162float(__float2bfloat16(y));
    h = packbf(hx, hy);
    l = packbf(x - hx, y - hy);
}
__device__ __forceinline__ void cpa16(uint32_t dst, const void* src) {
    asm volatile("cp.async.cg.shared.global [%0], [%1], 16;" :: "r"(dst), "l"(src));
}
#define CP_COMMIT() asm volatile("cp.async.commit_group;" ::: "memory")
#define CP_WAIT0()  asm volatile("cp.async.wait_group 0;" ::: "memory")

/* ------------------------------------------------------------------ */
/* Weight pre-split: fp32 -> bf16 hi/lo                                */
/* ------------------------------------------------------------------ */
template <int W>
__global__ void wsplit(const float4* __restrict__ src, int n4) {
    int i = blockIdx.x * 256 + threadIdx.x;
    if (i >= n4) return;
    float4 x = src[i];
    uint32_t h0, l0, h1, l1;
    split_pair(x.x, x.y, h0, l0);
    split_pair(x.z, x.w, h1, l1);
    uint2* dh; uint2* dl;
    if (W == 0)      { dh = (uint2*)g_wqh; dl = (uint2*)g_wql; }
    else if (W == 1) { dh = (uint2*)g_wkh; dl = (uint2*)g_wkl; }
    else if (W == 2) { dh = (uint2*)g_wvh; dl = (uint2*)g_wvl; }
    else             { dh = (uint2*)g_woh; dl = (uint2*)g_wol; }
    dh[i] = make_uint2(h0, h1);
    dl[i] = make_uint2(l0, l1);
}

/* ------------------------------------------------------------------ */
/* Gates                                                               */
/* ------------------------------------------------------------------ */
__global__ void gates_kernel(const float* __restrict__ k_src,
                             const float* __restrict__ sel_v,
                             const float* __restrict__ q_src,
                             const float* __restrict__ sel_o) {
    int w = threadIdx.x >> 5;
    int lane = threadIdx.x & 31;
    int t = blockIdx.x * 8 + w;

    const float* x; const float* sel; float* out;
    if (blockIdx.y == 0) { x = k_src; sel = sel_v; out = g_gv; }
    else                 { x = q_src; sel = sel_o; out = g_go; }

    const float4* xr = (const float4*)(x + (size_t)t * DD);
    const float4* sr = (const float4*)(sel + (size_t)lane * DD);
    float acc = 0.f;
#pragma unroll 8
    for (int i = 0; i < DD / 4; i++) {
        float4 a = xr[i], b = sr[i];
        acc += a.x * b.x + a.y * b.y + a.z * b.z + a.w * b.w;
    }
    float g = 1.f / (1.f + __expf(-acc));

    __shared__ float sh[8][32];
    sh[w][lane] = g;
    __syncwarp();

    if (lane < HH) {
        float vv[4];
#pragma unroll
        for (int e = 0; e < 4; e++) vv[e] = sh[w][lane * 4 + e];
        int i1 = 0; float m1 = vv[0];
#pragma unroll
        for (int e = 1; e < 4; e++) if (vv[e] > m1) { m1 = vv[e]; i1 = e; }
        int i2 = -1; float m2 = -1e30f;
#pragma unroll
        for (int e = 0; e < 4; e++) if (e != i1 && vv[e] > m2) { m2 = vv[e]; i2 = e; }
#pragma unroll
        for (int e = 0; e < 4; e++)
            out[(size_t)t * 32 + lane * 4 + e] = (e == i1 || e == i2) ? vv[e] : 0.f;
    }
}

/* ------------------------------------------------------------------ */
/* Pipelined tensor-core GEMM: block 128x128, Kc=32, double-buffered   */
/* cp.async staging of raw fp32 A + pre-split bf16 B; A converted      */
/* smem->smem off the MMA critical path.                               */
/* ------------------------------------------------------------------ */
#define AFSTR 36            /* fp32 staging row stride (floats) */
#define ASTR  40            /* bf16 tile row stride (elems) */
#define BSTR  136           /* modes 2/3 B row stride (elems) */

#define OAF 0
#define OAH 18432
#define OAL 28672
#define OBH 38912
template <int MODE> struct BufCfg {
    static constexpr int BQB = (MODE <= 1) ? 10240 : 8704;
    static constexpr int OBL = OBH + BQB;
    static constexpr int BUF = OBH + 2 * BQB;
};

template <int MODE>
__device__ __forceinline__ void tcg_stage(uint32_t sb, int c, int tid, int row0, int col0,
                                          const float* A,
                                          const __nv_bfloat16* Bph, const __nv_bfloat16* Bpl) {
    int k0 = c * 32;
    uint32_t bb = sb + (uint32_t)((c & 1) * BufCfg<MODE>::BUF);
    /* A fp32: 128 x 32 floats, cpa16 x1024 */
#pragma unroll
    for (int it = 0; it < 4; it++) {
        int idx = it * 256 + tid;
        int r = idx >> 3, c4 = (idx & 7) * 4;
        int kg = k0 + c4;
        int rt = row0 + r;
        const float* src;
        if (MODE <= 1) {
            src = A + (size_t)rt * 1024 + kg;
        } else if (MODE == 2) {
            src = A + (size_t)rt * 1024 + (kg & 1023);
        } else {
            int hh = kg >> 9, dh = kg & 127;
            src = g_res + (size_t)rt * 1024 + hh * 128 + dh;
        }
        cpa16(bb + OAF + (uint32_t)(r * AFSTR + c4) * 4, src);
    }
    /* B: 16KB hi+lo via cpa16 (8 elems per transfer) */
    if (MODE <= 1) {
#pragma unroll
        for (int it = 0; it < 4; it++) {
            int idx = it * 256 + tid;
            int aid = idx >> 9;
            int rem = idx & 511;
            int r = rem >> 2, c8 = (rem & 3) * 8;
            const __nv_bfloat16* s = aid ? Bpl : Bph;
            cpa16(bb + (aid ? BufCfg<MODE>::OBL : OBH) + (uint32_t)(r * ASTR + c8) * 2,
                  s + (size_t)(col0 + r) * 1024 + k0 + c8);
        }
    } else {
        constexpr int NLD = (MODE == 2) ? 128 : 1024;
#pragma unroll
        for (int it = 0; it < 4; it++) {
            int idx = it * 256 + tid;
            int aid = idx >> 9;
            int rem = idx & 511;
            int kr = rem >> 4, c8 = (rem & 15) * 8;
            const __nv_bfloat16* s = aid ? Bpl : Bph;
            cpa16(bb + (aid ? BufCfg<MODE>::OBL : OBH) + (uint32_t)(kr * BSTR + c8) * 2,
                  s + (size_t)(k0 + kr) * NLD + col0 + c8);
        }
    }
}

template <int MODE>
__device__ __forceinline__ void tcg_convert(char* dsm, int c, int tid, int row0, int hz,
                                            const float* gates) {
    int k0 = c * 32;
    char* bb = dsm + (c & 1) * BufCfg<MODE>::BUF;
#pragma unroll
    for (int it = 0; it < 4; it++) {
        int idx = it * 256 + tid;
        int r = idx >> 3, c4 = (idx & 7) * 4;
        int kg = k0 + c4;
        int rt = row0 + r;
        float gm = 1.f;
        if (MODE == 2) gm = gates[(size_t)rt * 32 + hz * 4 + (kg >> 10)];
        else if (MODE == 3) {
            int hh = kg >> 9, e = (kg >> 7) & 3;
            gm = gates[(size_t)rt * 32 + hh * 4 + e];
        }
        float4 x = *(const float4*)(bb + OAF + (size_t)(r * AFSTR + c4) * 4);
        x.x *= gm; x.y *= gm; x.z *= gm; x.w *= gm;
        uint32_t h0, l0, h1, l1;
        split_pair(x.x, x.y, h0, l0);
        split_pair(x.z, x.w, h1, l1);
        *(uint32_t*)(bb + OAH + (size_t)(r * ASTR + c4) * 2) = h0;
        *(uint32_t*)(bb + OAH + (size_t)(r * ASTR + c4 + 2) * 2) = h1;
        *(uint32_t*)(bb + OAL + (size_t)(r * ASTR + c4) * 2) = l0;
        *(uint32_t*)(bb + OAL + (size_t)(r * ASTR + c4 + 2) * 2) = l1;
    }
}

template <int MODE>
__global__ void __launch_bounds__(256)
tc_gemm(const float* __restrict__ A,
        float* __restrict__ C) {
    constexpr int KT = (MODE <= 1) ? 1024 : 4096;
    constexpr int NC = KT / 32;

    extern __shared__ char dsm[];
    uint32_t sb = smem_u32(dsm);

    int tid = threadIdx.x;
    int warp = tid >> 5, lane = tid & 31;
    int wm = warp & 3, wn = warp >> 2;
    int row0 = blockIdx.y * 128;
    int col0 = blockIdx.x * 128;
    int hz = blockIdx.z;

    const float* gates = (MODE == 2) ? g_gv : g_go;
    const __nv_bfloat16 *Bph, *Bpl;
    if (MODE == 0)      { Bph = g_wqh; Bpl = g_wql; }
    else if (MODE == 1) { Bph = g_wkh; Bpl = g_wkl; }
    else if (MODE == 2) { Bph = g_wvh + (size_t)hz * (EE * DD * DHH);
                          Bpl = g_wvl + (size_t)hz * (EE * DD * DHH); }
    else                { Bph = g_woh; Bpl = g_wol; }

    float d[2][8][4];
#pragma unroll
    for (int i = 0; i < 2; i++)
#pragma unroll
        for (int j = 0; j < 8; j++)
#pragma unroll
            for (int c = 0; c < 4; c++) d[i][j][c] = 0.f;

    /* prologue */
    tcg_stage<MODE>(sb, 0, tid, row0, col0, A, Bph, Bpl);
    CP_COMMIT();
    CP_WAIT0();
    __syncthreads();
    tcg_convert<MODE>(dsm, 0, tid, row0, hz, gates);
    __syncthreads();

    for (int c = 0; c < NC; c++) {
        if (c + 1 < NC) {
            tcg_stage<MODE>(sb, c + 1, tid, row0, col0, A, Bph, Bpl);
            CP_COMMIT();
        }

        /* ---- MMA phase on buffer c ---- */
        uint32_t bb = sb + (uint32_t)((c & 1) * BufCfg<MODE>::BUF);
#pragma unroll
        for (int ks = 0; ks < 2; ks++) {
            uint32_t ah[2][4], al[2][4];
#pragma unroll
            for (int mf = 0; mf < 2; mf++) {
                int off = (wm * 32 + mf * 16 + (lane & 15)) * ASTR + ks * 16 + (lane >> 4) * 8;
                ldsm4(ah[mf], bb + OAH + (uint32_t)off * 2);
                ldsm4(al[mf], bb + OAL + (uint32_t)off * 2);
            }
            uint32_t bfh[16], bfl[16];
            if (MODE <= 1) {
#pragma unroll
                for (int nf2 = 0; nf2 < 4; nf2++) {
                    int off = (wn * 64 + nf2 * 16 + (lane & 15)) * ASTR + ks * 16 + (lane >> 4) * 8;
                    uint32_t r[4];
                    ldsm4(r, bb + OBH + (uint32_t)off * 2);
                    bfh[nf2 * 4 + 0] = r[0]; bfh[nf2 * 4 + 1] = r[2];
                    bfh[nf2 * 4 + 2] = r[1]; bfh[nf2 * 4 + 3] = r[3];
                    ldsm4(r, bb + BufCfg<MODE>::OBL + (uint32_t)off * 2);
                    bfl[nf2 * 4 + 0] = r[0]; bfl[nf2 * 4 + 1] = r[2];
                    bfl[nf2 * 4 + 2] = r[1]; bfl[nf2 * 4 + 3] = r[3];
                }
            } else {
#pragma unroll
                for (int nf2 = 0; nf2 < 4; nf2++) {
                    int off = (ks * 16 + (lane & 15)) * BSTR + wn * 64 + nf2 * 16 + (lane >> 4) * 8;
                    uint32_t r[4];
                    ldsm4t(r, bb + OBH + (uint32_t)off * 2);
                    bfh[nf2 * 4 + 0] = r[0]; bfh[nf2 * 4 + 1] = r[1];
                    bfh[nf2 * 4 + 2] = r[2]; bfh[nf2 * 4 + 3] = r[3];
                    ldsm4t(r, bb + BufCfg<MODE>::OBL + (uint32_t)off * 2);
                    bfl[nf2 * 4 + 0] = r[0]; bfl[nf2 * 4 + 1] = r[1];
                    bfl[nf2 * 4 + 2] = r[2]; bfl[nf2 * 4 + 3] = r[3];
                }
            }
#pragma unroll
            for (int mf = 0; mf < 2; mf++)
#pragma unroll
                for (int nf = 0; nf < 8; nf++) {
                    mma16816(d[mf][nf], ah[mf], &bfh[nf * 2]);
                    mma16816(d[mf][nf], ah[mf], &bfl[nf * 2]);
                    mma16816(d[mf][nf], al[mf], &bfh[nf * 2]);
                }
        }

        if (c + 1 < NC) {
            CP_WAIT0();
            __syncthreads();
            tcg_convert<MODE>(dsm, c + 1, tid, row0, hz, gates);
            __syncthreads();
        }
    }

    /* ---- epilogue ---- */
    int ri = lane >> 2, c2 = (lane & 3) * 2;
#pragma unroll
    for (int mf = 0; mf < 2; mf++) {
#pragma unroll
        for (int nf = 0; nf < 8; nf++) {
            int col = col0 + wn * 64 + nf * 8 + c2;
#pragma unroll
            for (int hv = 0; hv < 2; hv++) {
                int row = row0 + wm * 32 + mf * 16 + ri + hv * 8;
                float v0 = d[mf][nf][hv * 2];
                float v1 = d[mf][nf][hv * 2 + 1];
                int bidx = row >> 11, sidx = row & 2047;
                if (MODE <= 1) {
                    v0 *= SCALE; v1 *= SCALE;
                    int hh = col >> 7, dh = col & 127;
                    size_t base = (((size_t)bidx * HH + hh) * SS + sidx) * DHH + dh;
                    uint32_t h, l;
                    split_pair(v0, v1, h, l);
                    __nv_bfloat16* dsth = (MODE == 0) ? g_qh : g_kh;
                    __nv_bfloat16* dstl = (MODE == 0) ? g_ql : g_kl;
                    *(uint32_t*)&dsth[base] = h;
                    *(uint32_t*)&dstl[base] = l;
                } else if (MODE == 2) {
                    size_t base = (((size_t)bidx * HH + hz) * SS + sidx) * DHH + col;
                    uint32_t h, l;
                    split_pair(v0, v1, h, l);
                    *(uint32_t*)&g_vh[base] = h;
                    *(uint32_t*)&g_vl[base] = l;
                } else {
                    float2 o = make_float2(v0, v1);
                    *(float2*)&C[(size_t)row * 1024 + col] = o;
                }
            }
        }
    }
}

/* ------------------------------------------------------------------ */
/* FA2 attention: BQ=256, BKV=64, 16 warps (512 thr), Q in smem,       */
/* split K/V single-buffer pipeline, register softmax. (R9, passing)   */
/* ------------------------------------------------------------------ */
#define QSE   136
#define O_QH  0
#define O_QL  (O_QH + 256 * QSE)
#define O_KH  (O_QL + 256 * QSE)
#define O_KL  (O_KH + 64 * QSE)
#define O_VH  (O_KL + 64 * QSE)
#define O_VL  (O_VH + 64 * QSE)
#define A_ELEMS (O_VL + 64 * QSE)
#define ATTN_BYTES (A_ELEMS * 2)   /* 208896 */

__device__ __forceinline__ void stage64(uint32_t smaddr, int baseElem, int kv0, int tid,
                                        const __nv_bfloat16* sh, const __nv_bfloat16* sl) {
#pragma unroll
    for (int it = 0; it < 4; it++) {
        int idx = it * 512 + tid;
        int aid = idx >> 10;
        int rem = idx & 1023;
        int r = rem >> 4, c8 = (rem & 15) * 8;
        const __nv_bfloat16* s = aid ? sl : sh;
        cpa16(smaddr + (uint32_t)(baseElem + aid * (64 * QSE) + r * QSE + c8) * 2,
              s + (size_t)(kv0 + r) * DHH + c8);
    }
}

__global__ void __launch_bounds__(512, 1) attn_fa() {
    extern __shared__ __nv_bfloat16 sm[];
    uint32_t smaddr = smem_u32(sm);

    int tid = threadIdx.x;
    int warp = tid >> 5, lane = tid & 31;
    int bh = blockIdx.y;
    int q0 = blockIdx.x * 256;

    const __nv_bfloat16* qh = g_qh + (size_t)bh * SS * DHH;
    const __nv_bfloat16* ql = g_ql + (size_t)bh * SS * DHH;
    const __nv_bfloat16* kh = g_kh + (size_t)bh * SS * DHH;
    const __nv_bfloat16* kl = g_kl + (size_t)bh * SS * DHH;
    const __nv_bfloat16* vh = g_vh + (size_t)bh * SS * DHH;
    const __nv_bfloat16* vl = g_vl + (size_t)bh * SS * DHH;

#pragma unroll
    for (int it = 0; it < 16; it++) {
        int idx = it * 512 + tid;
        int aid = idx >> 12;
        int rem = idx & 4095;
        int r = rem >> 4, c8 = (rem & 15) * 8;
        const __nv_bfloat16* s = aid ? ql : qh;
        cpa16(smaddr + (uint32_t)(aid * (256 * QSE) + r * QSE + c8) * 2,
              s + (size_t)(q0 + r) * DHH + c8);
    }
    CP_COMMIT();

    float oacc[16][4];
#pragma unroll
    for (int j = 0; j < 16; j++)
#pragma unroll
        for (int c = 0; c < 4; c++) oacc[j][c] = 0.f;
    float mold[2] = { -1e30f, -1e30f };
    float lsum[2] = { 0.f, 0.f };

    CP_WAIT0();
    __syncthreads();

    stage64(smaddr, O_KH, 0, tid, kh, kl);
    CP_COMMIT();

    for (int kvi = 0; kvi < SS / 64; kvi++) {
        int kv0 = kvi * 64;
        CP_WAIT0();
        __syncthreads();

        stage64(smaddr, O_VH, kv0, tid, vh, vl);
        CP_COMMIT();

        float sacc[8][4];
#pragma unroll
        for (int j = 0; j < 8; j++)
#pragma unroll
            for (int c = 0; c < 4; c++) sacc[j][c] = 0.f;

#pragma unroll
        for (int ks = 0; ks < 8; ks++) {
            uint32_t qfh[4], qfl[4];
            {
                int off = (warp * 16 + (lane & 15)) * QSE + ks * 16 + (lane >> 4) * 8;
                ldsm4(qfh, smaddr + (uint32_t)(O_QH + off) * 2);
                ldsm4(qfl, smaddr + (uint32_t)(O_QL + off) * 2);
            }
#pragma unroll
            for (int ng = 0; ng < 4; ng++) {
                int off = (ng * 16 + (lane & 15)) * QSE + ks * 16 + (lane >> 4) * 8;
                uint32_t rh[4], rl[4];
                ldsm4(rh, smaddr + (uint32_t)(O_KH + off) * 2);
                ldsm4(rl, smaddr + (uint32_t)(O_KL + off) * 2);
                uint32_t b0h[2] = { rh[0], rh[2] }, b1h[2] = { rh[1], rh[3] };
                uint32_t b0l[2] = { rl[0], rl[2] }, b1l[2] = { rl[1], rl[3] };
                mma16816(sacc[ng * 2], qfh, b0h);
                mma16816(sacc[ng * 2], qfh, b0l);
                mma16816(sacc[ng * 2], qfl, b0h);
                mma16816(sacc[ng * 2 + 1], qfh, b1h);
                mma16816(sacc[ng * 2 + 1], qfh, b1l);
                mma16816(sacc[ng * 2 + 1], qfl, b1h);
            }
        }

        float corr[2];
#pragma unroll
        for (int hf = 0; hf < 2; hf++) {
            float mx = -1e30f;
#pragma unroll
            for (int nf = 0; nf < 8; nf++) {
                mx = fmaxf(mx, sacc[nf][hf * 2]);
                mx = fmaxf(mx, sacc[nf][hf * 2 + 1]);
            }
            mx = fmaxf(mx, __shfl_xor_sync(0xffffffffu, mx, 1));
            mx = fmaxf(mx, __shfl_xor_sync(0xffffffffu, mx, 2));
            float mnew = fmaxf(mold[hf], mx);
            corr[hf] = __expf(mold[hf] - mnew);
            mold[hf] = mnew;
            float ls = 0.f;
#pragma unroll
            for (int nf = 0; nf < 8; nf++) {
                float p0 = __expf(sacc[nf][hf * 2] - mnew);
                float p1 = __expf(sacc[nf][hf * 2 + 1] - mnew);
                sacc[nf][hf * 2] = p0;
                sacc[nf][hf * 2 + 1] = p1;
                ls += p0 + p1;
            }
            ls += __shfl_xor_sync(0xffffffffu, ls, 1);
            ls += __shfl_xor_sync(0xffffffffu, ls, 2);
            lsum[hf] = lsum[hf] * corr[hf] + ls;
        }
#pragma unroll
        for (int nf = 0; nf < 16; nf++) {
            oacc[nf][0] *= corr[0]; oacc[nf][1] *= corr[0];
            oacc[nf][2] *= corr[1]; oacc[nf][3] *= corr[1];
        }

        CP_WAIT0();
        __syncthreads();

        if (kvi + 1 < SS / 64) {
            stage64(smaddr, O_KH, kv0 + 64, tid, kh, kl);
            CP_COMMIT();
        }

#pragma unroll
        for (int kk = 0; kk < 4; kk++) {
            uint32_t ph[4], pl[4];
            split_pair(sacc[kk * 2][0],     sacc[kk * 2][1],     ph[0], pl[0]);
            split_pair(sacc[kk * 2][2],     sacc[kk * 2][3],     ph[1], pl[1]);
            split_pair(sacc[kk * 2 + 1][0], sacc[kk * 2 + 1][1], ph[2], pl[2]);
            split_pair(sacc[kk * 2 + 1][2], sacc[kk * 2 + 1][3], ph[3], pl[3]);
#pragma unroll
            for (int ng = 0; ng < 8; ng++) {
                int off = (kk * 16 + (lane & 15)) * QSE + ng * 16 + (lane >> 4) * 8;
                uint32_t rh[4], rl[4];
                ldsm4t(rh, smaddr + (uint32_t)(O_VH + off) * 2);
                ldsm4t(rl, smaddr + (uint32_t)(O_VL + off) * 2);
                uint32_t b0h[2] = { rh[0], rh[1] }, b1h[2] = { rh[2], rh[3] };
                uint32_t b0l[2] = { rl[0], rl[1] }, b1l[2] = { rl[2], rl[3] };
                mma16816(oacc[ng * 2], ph, b0h);
                mma16816(oacc[ng * 2], ph, b0l);
                mma16816(oacc[ng * 2], pl, b0h);
                mma16816(oacc[ng * 2 + 1], ph, b1h);
                mma16816(oacc[ng * 2 + 1], ph, b1l);
                mma16816(oacc[ng * 2 + 1], pl, b1h);
            }
        }
    }

    {
        int b = bh >> 3;
        int h2 = bh & 7;
        int ri = lane >> 2;
        int cc = (lane & 3) * 2;
        float li0 = 1.f / lsum[0];
        float li1 = 1.f / lsum[1];
        size_t t0 = (size_t)b * SS + q0 + warp * 16 + ri;
#pragma unroll
        for (int nf = 0; nf < 16; nf++) {
            int col = nf * 8 + cc;
            float2 o0 = make_float2(oacc[nf][0] * li0, oacc[nf][1] * li0);
            float2 o1 = make_float2(oacc[nf][2] * li1, oacc[nf][3] * li1);
            *(float2*)&g_res[t0 * 1024 + h2 * 128 + col] = o0;
            *(float2*)&g_res[(t0 + 8) * 1024 + h2 * 128 + col] = o1;
        }
    }
}

/* ------------------------------------------------------------------ */
extern "C" void kernel_launch(void* const* d_in, const int* in_sizes, int n_in,
                              void* d_out, int out_size) {
    (void)in_sizes; (void)n_in; (void)out_size;
    const float* q_src = (const float*)d_in[0];
    const float* k_src = (const float*)d_in[1];
    const float* v_src = (const float*)d_in[2];
    const float* Wq    = (const float*)d_in[3];
    const float* Wk    = (const float*)d_in[4];
    const float* Wv    = (const float*)d_in[5];
    const float* Wo    = (const float*)d_in[6];
    const float* sel_v = (const float*)d_in[7];
    const float* sel_o = (const float*)d_in[8];
    float* out = (float*)d_out;

    const int SM01 = 2 * BufCfg<0>::BUF;   /* 118784 */
    const int SM23 = 2 * BufCfg<2>::BUF;   /* 112640 */

    cudaFuncSetAttribute(attn_fa, cudaFuncAttributeMaxDynamicSharedMemorySize, ATTN_BYTES);
    cudaFuncSetAttribute(tc_gemm<0>, cudaFuncAttributeMaxDynamicSharedMemorySize, SM01);
    cudaFuncSetAttribute(tc_gemm<1>, cudaFuncAttributeMaxDynamicSharedMemorySize, SM01);
    cudaFuncSetAttribute(tc_gemm<2>, cudaFuncAttributeMaxDynamicSharedMemorySize, SM23);
    cudaFuncSetAttribute(tc_gemm<3>, cudaFuncAttributeMaxDynamicSharedMemorySize, SM23);

    wsplit<0><<<(DD * DD / 4 + 255) / 256, 256>>>((const float4*)Wq, DD * DD / 4);
    wsplit<1><<<(DD * DD / 4 + 255) / 256, 256>>>((const float4*)Wk, DD * DD / 4);
    wsplit<2><<<(HH * EE * DD * DHH / 4 + 255) / 256, 256>>>((const float4*)Wv, HH * EE * DD * DHH / 4);
    wsplit<3><<<(HH * EE * DHH * DD / 4 + 255) / 256, 256>>>((const float4*)Wo, HH * EE * DHH * DD / 4);
    gates_kernel<<<dim3(TOK / 8, 2), 256>>>(k_src, sel_v, q_src, sel_o);

    tc_gemm<0><<<dim3(8, 32), 256, SM01>>>(q_src, nullptr);
    tc_gemm<1><<<dim3(8, 32), 256, SM01>>>(k_src, nullptr);
    tc_gemm<2><<<dim3(1, 32, 8), 256, SM23>>>(v_src, nullptr);
    attn_fa<<<dim3(SS / 256, BB * HH), 512, ATTN_BYTES>>>();
    tc_gemm<3><<<dim3(8, 32), 256, SM23>>>(nullptr, out);
}

// round 12
// speedup vs baseline: 1.0940x; 1.0940x over previous
#include <cuda_runtime.h>
#include <cuda_bf16.h>
#include <cstdint>
#include <math.h>

#define BB   2
#define SS   2048
#define DD   1024
#define HH   8
#define EE   4
#define DHH  128
#define TOK  (BB*SS)
#define SCALE 0.29730177875068026f      /* 128^-0.25 */

/* ------------------------------------------------------------------ */
/* scratch (device globals)                                            */
/* ------------------------------------------------------------------ */
__device__ float g_res[TOK * DD];      /* [t, h*128+dh] */
__device__ float g_gv[TOK * HH * EE];
__device__ float g_go[TOK * HH * EE];

/* pre-split activations: [b,h,s,dh] layout */
__device__ __nv_bfloat16 g_qh[TOK * DD], g_ql[TOK * DD];
__device__ __nv_bfloat16 g_kh[TOK * DD], g_kl[TOK * DD];
__device__ __nv_bfloat16 g_vh[TOK * DD], g_vl[TOK * DD];

/* pre-split weights */
__device__ __nv_bfloat16 g_wqh[DD * DD], g_wql[DD * DD];
__device__ __nv_bfloat16 g_wkh[DD * DD], g_wkl[DD * DD];
__device__ __nv_bfloat16 g_wvh[HH * EE * DD * DHH], g_wvl[HH * EE * DD * DHH];
__device__ __nv_bfloat16 g_woh[HH * EE * DHH * DD], g_wol[HH * EE * DHH * DD];

/* ------------------------------------------------------------------ */
/* helpers                                                             */
/* ------------------------------------------------------------------ */
__device__ __forceinline__ uint32_t smem_u32(const void* p) {
    return (uint32_t)__cvta_generic_to_shared(p);
}
__device__ __forceinline__ void ldsm4(uint32_t* r, uint32_t a) {
    asm volatile("ldmatrix.sync.aligned.m8n8.x4.shared.b16 {%0,%1,%2,%3}, [%4];"
                 : "=r"(r[0]), "=r"(r[1]), "=r"(r[2]), "=r"(r[3]) : "r"(a));
}
__device__ __forceinline__ void ldsm4t(uint32_t* r, uint32_t a) {
    asm volatile("ldmatrix.sync.aligned.m8n8.x4.trans.shared.b16 {%0,%1,%2,%3}, [%4];"
                 : "=r"(r[0]), "=r"(r[1]), "=r"(r[2]), "=r"(r[3]) : "r"(a));
}
__device__ __forceinline__ void mma16816(float* d, const uint32_t* a, const uint32_t* b) {
    asm volatile(
        "mma.sync.aligned.m16n8k16.row.col.f32.bf16.bf16.f32 "
        "{%0,%1,%2,%3}, {%4,%5,%6,%7}, {%8,%9}, {%0,%1,%2,%3};"
        : "+f"(d[0]), "+f"(d[1]), "+f"(d[2]), "+f"(d[3])
        : "r"(a[0]), "r"(a[1]), "r"(a[2]), "r"(a[3]), "r"(b[0]), "r"(b[1]));
}
__device__ __forceinline__ uint32_t packbf(float x, float y) {
    __nv_bfloat162 t = __floats2bfloat162_rn(x, y);
    return *reinterpret_cast<uint32_t*>(&t);
}
__device__ __forceinline__ void split_pair(float x, float y, uint32_t& h, uint32_t& l) {
    float hx = __bfloat162float(__float2bfloat16(x));
    float hy = __bfloat162float(__float2bfloat16(y));
    h = packbf(hx, hy);
    l = packbf(x - hx, y - hy);
}
__device__ __forceinline__ void cpa16(uint32_t dst, const void* src) {
    asm volatile("cp.async.cg.shared.global [%0], [%1], 16;" :: "r"(dst), "l"(src));
}
#define CP_COMMIT() asm volatile("cp.async.commit_group;" ::: "memory")
#define CP_WAIT0()  asm volatile("cp.async.wait_group 0;" ::: "memory")
#define CP_WAIT1()  asm volatile("cp.async.wait_group 1;" ::: "memory")

/* ------------------------------------------------------------------ */
/* Weight pre-split: fp32 -> bf16 hi/lo                                */
/* ------------------------------------------------------------------ */
template <int W>
__global__ void wsplit(const float4* __restrict__ src, int n4) {
    int i = blockIdx.x * 256 + threadIdx.x;
    if (i >= n4) return;
    float4 x = src[i];
    uint32_t h0, l0, h1, l1;
    split_pair(x.x, x.y, h0, l0);
    split_pair(x.z, x.w, h1, l1);
    uint2* dh; uint2* dl;
    if (W == 0)      { dh = (uint2*)g_wqh; dl = (uint2*)g_wql; }
    else if (W == 1) { dh = (uint2*)g_wkh; dl = (uint2*)g_wkl; }
    else if (W == 2) { dh = (uint2*)g_wvh; dl = (uint2*)g_wvl; }
    else             { dh = (uint2*)g_woh; dl = (uint2*)g_wol; }
    dh[i] = make_uint2(h0, h1);
    dl[i] = make_uint2(l0, l1);
}

/* ------------------------------------------------------------------ */
/* Gates                                                               */
/* ------------------------------------------------------------------ */
__global__ void gates_kernel(const float* __restrict__ k_src,
                             const float* __restrict__ sel_v,
                             const float* __restrict__ q_src,
                             const float* __restrict__ sel_o) {
    int w = threadIdx.x >> 5;
    int lane = threadIdx.x & 31;
    int t = blockIdx.x * 8 + w;

    const float* x; const float* sel; float* out;
    if (blockIdx.y == 0) { x = k_src; sel = sel_v; out = g_gv; }
    else                 { x = q_src; sel = sel_o; out = g_go; }

    const float4* xr = (const float4*)(x + (size_t)t * DD);
    const float4* sr = (const float4*)(sel + (size_t)lane * DD);
    float acc = 0.f;
#pragma unroll 8
    for (int i = 0; i < DD / 4; i++) {
        float4 a = xr[i], b = sr[i];
        acc += a.x * b.x + a.y * b.y + a.z * b.z + a.w * b.w;
    }
    float g = 1.f / (1.f + __expf(-acc));

    __shared__ float sh[8][32];
    sh[w][lane] = g;
    __syncwarp();

    if (lane < HH) {
        float vv[4];
#pragma unroll
        for (int e = 0; e < 4; e++) vv[e] = sh[w][lane * 4 + e];
        int i1 = 0; float m1 = vv[0];
#pragma unroll
        for (int e = 1; e < 4; e++) if (vv[e] > m1) { m1 = vv[e]; i1 = e; }
        int i2 = -1; float m2 = -1e30f;
#pragma unroll
        for (int e = 0; e < 4; e++) if (e != i1 && vv[e] > m2) { m2 = vv[e]; i2 = e; }
#pragma unroll
        for (int e = 0; e < 4; e++)
            out[(size_t)t * 32 + lane * 4 + e] = (e == i1 || e == i2) ? vv[e] : 0.f;
    }
}

/* ------------------------------------------------------------------ */
/* Tensor-core GEMM (mma.sync), block 128x128, Kc=64, split bf16.      */
/* B side from pre-split global bf16 (pure uint4 copy). Dynamic smem.  */
/* MODE 0: Q proj, 1: K proj, 2: V expert build, 3: O expert build     */
/* ------------------------------------------------------------------ */
#define AST  72             /* A row stride (elems), 64 cols + 8 pad */
#define BSTR 136            /* modes 2/3 B row stride */

/* byte offsets in dynamic smem */
#define OAH 0
#define OAL 18432
#define OBH 36864
template <int MODE> struct GCfg {
    static constexpr int BQ  = (MODE <= 1) ? (128 * AST * 2) : (64 * BSTR * 2);
    static constexpr int OBL = OBH + BQ;
    static constexpr int SMB = OBH + 2 * BQ;
};

template <int MODE>
__global__ void __launch_bounds__(256)
tc_gemm(const float* __restrict__ A,
        float* __restrict__ C) {
    constexpr int KT = (MODE <= 1) ? 1024 : 4096;

    extern __shared__ char dsm[];
    __nv_bfloat16* Ah = (__nv_bfloat16*)(dsm + OAH);
    __nv_bfloat16* Al = (__nv_bfloat16*)(dsm + OAL);
    __nv_bfloat16* Bh = (__nv_bfloat16*)(dsm + OBH);
    __nv_bfloat16* Bl = (__nv_bfloat16*)(dsm + GCfg<MODE>::OBL);

    int tid = threadIdx.x;
    int warp = tid >> 5, lane = tid & 31;
    int wm = warp & 3, wn = warp >> 2;
    int row0 = blockIdx.y * 128;
    int col0 = blockIdx.x * 128;
    int hz = blockIdx.z;

    const float* gates = (MODE == 2) ? g_gv : g_go;
    const __nv_bfloat16 *Bph, *Bpl;
    if (MODE == 0)      { Bph = g_wqh; Bpl = g_wql; }
    else if (MODE == 1) { Bph = g_wkh; Bpl = g_wkl; }
    else if (MODE == 2) { Bph = g_wvh + (size_t)hz * (EE * DD * DHH);
                          Bpl = g_wvl + (size_t)hz * (EE * DD * DHH); }
    else                { Bph = g_woh; Bpl = g_wol; }

    float d[2][8][4];
#pragma unroll
    for (int i = 0; i < 2; i++)
#pragma unroll
        for (int j = 0; j < 8; j++)
#pragma unroll
            for (int c = 0; c < 4; c++) d[i][j][c] = 0.f;

    for (int k0 = 0; k0 < KT; k0 += 64) {
        /* ---- stage A: 128 rows x 64 cols fp32 -> gated split ---- */
#pragma unroll
        for (int it = 0; it < 8; it++) {
            int idx = it * 256 + tid;
            int r = idx >> 4, c4 = (idx & 15) * 4;
            int kg = k0 + c4;
            int rt = row0 + r;
            const float* src;
            float gm = 1.f;
            if (MODE <= 1) {
                src = A + (size_t)rt * 1024 + kg;
            } else if (MODE == 2) {
                src = A + (size_t)rt * 1024 + (kg & 1023);
                gm = gates[(size_t)rt * 32 + hz * 4 + (kg >> 10)];
            } else {
                int hh = kg >> 9, e = (kg >> 7) & 3, dh = kg & 127;
                src = g_res + (size_t)rt * 1024 + hh * 128 + dh;
                gm = gates[(size_t)rt * 32 + hh * 4 + e];
            }
            float4 x = *(const float4*)src;
            x.x *= gm; x.y *= gm; x.z *= gm; x.w *= gm;
            uint32_t h0, l0, h1, l1;
            split_pair(x.x, x.y, h0, l0);
            split_pair(x.z, x.w, h1, l1);
            *(uint32_t*)&Ah[r * AST + c4] = h0;
            *(uint32_t*)&Ah[r * AST + c4 + 2] = h1;
            *(uint32_t*)&Al[r * AST + c4] = l0;
            *(uint32_t*)&Al[r * AST + c4 + 2] = l1;
        }
        /* ---- stage B (pre-split bf16, pure uint4 copy) ---- */
        if (MODE <= 1) {
            /* [n=128][k=64], hi then lo: 1024 uint4 each */
#pragma unroll
            for (int it = 0; it < 8; it++) {
                int idx = it * 256 + tid;
                int aid = idx >> 10;
                int rem = idx & 1023;
                int r = rem >> 3, c8 = (rem & 7) * 8;
                size_t so = (size_t)(col0 + r) * 1024 + k0 + c8;
                if (aid == 0) *(uint4*)&Bh[r * AST + c8] = *(const uint4*)(Bph + so);
                else          *(uint4*)&Bl[r * AST + c8] = *(const uint4*)(Bpl + so);
            }
        } else {
            constexpr int NLD = (MODE == 2) ? 128 : 1024;
            /* [k=64][n=128], hi then lo */
#pragma unroll
            for (int it = 0; it < 8; it++) {
                int idx = it * 256 + tid;
                int aid = idx >> 10;
                int rem = idx & 1023;
                int kr = rem >> 4, c8 = (rem & 15) * 8;
                size_t so = (size_t)(k0 + kr) * NLD + col0 + c8;
                if (aid == 0) *(uint4*)&Bh[kr * BSTR + c8] = *(const uint4*)(Bph + so);
                else          *(uint4*)&Bl[kr * BSTR + c8] = *(const uint4*)(Bpl + so);
            }
        }
        __syncthreads();

#pragma unroll
        for (int ks = 0; ks < 4; ks++) {
            uint32_t ah[2][4], al[2][4];
#pragma unroll
            for (int mf = 0; mf < 2; mf++) {
                int off = (wm * 32 + mf * 16 + (lane & 15)) * AST + ks * 16 + (lane >> 4) * 8;
                ldsm4(ah[mf], smem_u32(&Ah[off]));
                ldsm4(al[mf], smem_u32(&Al[off]));
            }
            uint32_t bfh[16], bfl[16];
            if (MODE <= 1) {
#pragma unroll
                for (int nf2 = 0; nf2 < 4; nf2++) {
                    int off = (wn * 64 + nf2 * 16 + (lane & 15)) * AST + ks * 16 + (lane >> 4) * 8;
                    uint32_t r[4];
                    ldsm4(r, smem_u32(&Bh[off]));
                    bfh[nf2 * 4 + 0] = r[0]; bfh[nf2 * 4 + 1] = r[2];
                    bfh[nf2 * 4 + 2] = r[1]; bfh[nf2 * 4 + 3] = r[3];
                    ldsm4(r, smem_u32(&Bl[off]));
                    bfl[nf2 * 4 + 0] = r[0]; bfl[nf2 * 4 + 1] = r[2];
                    bfl[nf2 * 4 + 2] = r[1]; bfl[nf2 * 4 + 3] = r[3];
                }
            } else {
#pragma unroll
                for (int nf2 = 0; nf2 < 4; nf2++) {
                    int off = (ks * 16 + (lane & 15)) * BSTR + wn * 64 + nf2 * 16 + (lane >> 4) * 8;
                    uint32_t r[4];
                    ldsm4t(r, smem_u32(&Bh[off]));
                    bfh[nf2 * 4 + 0] = r[0]; bfh[nf2 * 4 + 1] = r[1];
                    bfh[nf2 * 4 + 2] = r[2]; bfh[nf2 * 4 + 3] = r[3];
                    ldsm4t(r, smem_u32(&Bl[off]));
                    bfl[nf2 * 4 + 0] = r[0]; bfl[nf2 * 4 + 1] = r[1];
                    bfl[nf2 * 4 + 2] = r[2]; bfl[nf2 * 4 + 3] = r[3];
                }
            }
#pragma unroll
            for (int mf = 0; mf < 2; mf++)
#pragma unroll
                for (int nf = 0; nf < 8; nf++) {
                    mma16816(d[mf][nf], ah[mf], &bfh[nf * 2]);
                    mma16816(d[mf][nf], ah[mf], &bfl[nf * 2]);
                    mma16816(d[mf][nf], al[mf], &bfh[nf * 2]);
                }
        }
        __syncthreads();
    }

    /* ---- epilogue ---- */
    int ri = lane >> 2, c2 = (lane & 3) * 2;
#pragma unroll
    for (int mf = 0; mf < 2; mf++) {
#pragma unroll
        for (int nf = 0; nf < 8; nf++) {
            int col = col0 + wn * 64 + nf * 8 + c2;
#pragma unroll
            for (int hv = 0; hv < 2; hv++) {
                int row = row0 + wm * 32 + mf * 16 + ri + hv * 8;
                float v0 = d[mf][nf][hv * 2];
                float v1 = d[mf][nf][hv * 2 + 1];
                int bidx = row >> 11, sidx = row & 2047;
                if (MODE <= 1) {
                    v0 *= SCALE; v1 *= SCALE;
                    int hh = col >> 7, dh = col & 127;
                    size_t base = (((size_t)bidx * HH + hh) * SS + sidx) * DHH + dh;
                    uint32_t h, l;
                    split_pair(v0, v1, h, l);
                    __nv_bfloat16* dsth = (MODE == 0) ? g_qh : g_kh;
                    __nv_bfloat16* dstl = (MODE == 0) ? g_ql : g_kl;
                    *(uint32_t*)&dsth[base] = h;
                    *(uint32_t*)&dstl[base] = l;
                } else if (MODE == 2) {
                    size_t base = (((size_t)bidx * HH + hz) * SS + sidx) * DHH + col;
                    uint32_t h, l;
                    split_pair(v0, v1, h, l);
                    *(uint32_t*)&g_vh[base] = h;
                    *(uint32_t*)&g_vl[base] = l;
                } else {
                    float2 o = make_float2(v0, v1);
                    *(float2*)&C[(size_t)row * 1024 + col] = o;
                }
            }
        }
    }
}

/* ------------------------------------------------------------------ */
/* FA2 attention (R8, best measured): BQ=128, BKV=64, 8 warps,         */
/* Q-frags in regs, cp.async double-buffered K/V, register softmax.    */
/* ------------------------------------------------------------------ */
#define KVB  8704                 /* 64*136 elems */
#define BUFE (4 * KVB)
#define ATTN_BYTES (2 * BUFE * 2) /* 139264 */

__device__ __forceinline__ void stage_kv(uint32_t smaddr, int bufe, int kv0, int tid,
                                         const __nv_bfloat16* kh, const __nv_bfloat16* kl,
                                         const __nv_bfloat16* vh, const __nv_bfloat16* vl) {
#pragma unroll
    for (int it = 0; it < 16; it++) {
        int idx = it * 256 + tid;
        int aid = idx >> 10;
        int rem = idx & 1023;
        int r = rem >> 4, c8 = (rem & 15) * 8;
        const __nv_bfloat16* s = (aid == 0) ? kh : (aid == 1) ? kl : (aid == 2) ? vh : vl;
        cpa16(smaddr + (uint32_t)(bufe + aid * KVB + r * 136 + c8) * 2,
              s + (size_t)(kv0 + r) * DHH + c8);
    }
}

__global__ void __launch_bounds__(256, 1) attn_fa() {
    extern __shared__ __nv_bfloat16 sm[];
    uint32_t smaddr = smem_u32(sm);

    int tid = threadIdx.x;
    int warp = tid >> 5, lane = tid & 31;
    int bh = blockIdx.y;
    int q0 = blockIdx.x * 128;

    const __nv_bfloat16* qh = g_qh + (size_t)bh * SS * DHH;
    const __nv_bfloat16* ql = g_ql + (size_t)bh * SS * DHH;
    const __nv_bfloat16* kh = g_kh + (size_t)bh * SS * DHH;
    const __nv_bfloat16* kl = g_kl + (size_t)bh * SS * DHH;
    const __nv_bfloat16* vh = g_vh + (size_t)bh * SS * DHH;
    const __nv_bfloat16* vl = g_vl + (size_t)bh * SS * DHH;

    /* ---- stage Q into buf0 space, load frags to registers ---- */
#pragma unroll
    for (int it = 0; it < 16; it++) {
        int idx = it * 256 + tid;
        int aid = idx >> 11;
        int rem = idx & 2047;
        int r = rem >> 4, c8 = (rem & 15) * 8;
        const __nv_bfloat16* s = aid ? ql : qh;
        cpa16(smaddr + (uint32_t)(aid * (128 * 136) + r * 136 + c8) * 2,
              s + (size_t)(q0 + r) * DHH + c8);
    }
    CP_COMMIT();
    CP_WAIT0();
    __syncthreads();

    uint32_t qfh[8][4], qfl[8][4];
#pragma unroll
    for (int ks = 0; ks < 8; ks++) {
        int off = (warp * 16 + (lane & 15)) * 136 + ks * 16 + (lane >> 4) * 8;
        ldsm4(qfh[ks], smaddr + (uint32_t)off * 2);
        ldsm4(qfl[ks], smaddr + (uint32_t)(128 * 136 + off) * 2);
    }
    __syncthreads();

    float oacc[16][4];
#pragma unroll
    for (int j = 0; j < 16; j++)
#pragma unroll
        for (int c = 0; c < 4; c++) oacc[j][c] = 0.f;
    float mold[2] = { -1e30f, -1e30f };
    float lsum[2] = { 0.f, 0.f };

    stage_kv(smaddr, 0, 0, tid, kh, kl, vh, vl);
    CP_COMMIT();

    for (int kvi = 0; kvi < SS / 64; kvi++) {
        int bufe = (kvi & 1) * BUFE;
        if (kvi + 1 < SS / 64)
            stage_kv(smaddr, ((kvi + 1) & 1) * BUFE, (kvi + 1) * 64, tid, kh, kl, vh, vl);
        CP_COMMIT();
        CP_WAIT1();
        __syncthreads();

        float sacc[8][4];
#pragma unroll
        for (int j = 0; j < 8; j++)
#pragma unroll
            for (int c = 0; c < 4; c++) sacc[j][c] = 0.f;

#pragma unroll
        for (int ks = 0; ks < 8; ks++) {
#pragma unroll
            for (int ng = 0; ng < 4; ng++) {
                int off = (ng * 16 + (lane & 15)) * 136 + ks * 16 + (lane >> 4) * 8;
                uint32_t rh[4], rl[4];
                ldsm4(rh, smaddr + (uint32_t)(bufe + off) * 2);
                ldsm4(rl, smaddr + (uint32_t)(bufe + KVB + off) * 2);
                uint32_t b0h[2] = { rh[0], rh[2] }, b1h[2] = { rh[1], rh[3] };
                uint32_t b0l[2] = { rl[0], rl[2] }, b1l[2] = { rl[1], rl[3] };
                mma16816(sacc[ng * 2], qfh[ks], b0h);
                mma16816(sacc[ng * 2], qfh[ks], b0l);
                mma16816(sacc[ng * 2], qfl[ks], b0h);
                mma16816(sacc[ng * 2 + 1], qfh[ks], b1h);
                mma16816(sacc[ng * 2 + 1], qfh[ks], b1l);
                mma16816(sacc[ng * 2 + 1], qfl[ks], b1h);
            }
        }

        float corr[2];
#pragma unroll
        for (int hf = 0; hf < 2; hf++) {
            float mx = -1e30f;
#pragma unroll
            for (int nf = 0; nf < 8; nf++) {
                mx = fmaxf(mx, sacc[nf][hf * 2]);
                mx = fmaxf(mx, sacc[nf][hf * 2 + 1]);
            }
            mx = fmaxf(mx, __shfl_xor_sync(0xffffffffu, mx, 1));
            mx = fmaxf(mx, __shfl_xor_sync(0xffffffffu, mx, 2));
            float mnew = fmaxf(mold[hf], mx);
            corr[hf] = __expf(mold[hf] - mnew);
            mold[hf] = mnew;
            float ls = 0.f;
#pragma unroll
            for (int nf = 0; nf < 8; nf++) {
                float p0 = __expf(sacc[nf][hf * 2] - mnew);
                float p1 = __expf(sacc[nf][hf * 2 + 1] - mnew);
                sacc[nf][hf * 2] = p0;
                sacc[nf][hf * 2 + 1] = p1;
                ls += p0 + p1;
            }
            ls += __shfl_xor_sync(0xffffffffu, ls, 1);
            ls += __shfl_xor_sync(0xffffffffu, ls, 2);
            lsum[hf] = lsum[hf] * corr[hf] + ls;
        }
#pragma unroll
        for (int nf = 0; nf < 16; nf++) {
            oacc[nf][0] *= corr[0]; oacc[nf][1] *= corr[0];
            oacc[nf][2] *= corr[1]; oacc[nf][3] *= corr[1];
        }

#pragma unroll
        for (int kk = 0; kk < 4; kk++) {
            uint32_t ph[4], pl[4];
            split_pair(sacc[kk * 2][0],     sacc[kk * 2][1],     ph[0], pl[0]);
            split_pair(sacc[kk * 2][2],     sacc[kk * 2][3],     ph[1], pl[1]);
            split_pair(sacc[kk * 2 + 1][0], sacc[kk * 2 + 1][1], ph[2], pl[2]);
            split_pair(sacc[kk * 2 + 1][2], sacc[kk * 2 + 1][3], ph[3], pl[3]);
#pragma unroll
            for (int ng = 0; ng < 8; ng++) {
                int off = (kk * 16 + (lane & 15)) * 136 + ng * 16 + (lane >> 4) * 8;
                uint32_t rh[4], rl[4];
                ldsm4t(rh, smaddr + (uint32_t)(bufe + 2 * KVB + off) * 2);
                ldsm4t(rl, smaddr + (uint32_t)(bufe + 3 * KVB + off) * 2);
                uint32_t b0h[2] = { rh[0], rh[1] }, b1h[2] = { rh[2], rh[3] };
                uint32_t b0l[2] = { rl[0], rl[1] }, b1l[2] = { rl[2], rl[3] };
                mma16816(oacc[ng * 2], ph, b0h);
                mma16816(oacc[ng * 2], ph, b0l);
                mma16816(oacc[ng * 2], pl, b0h);
                mma16816(oacc[ng * 2 + 1], ph, b1h);
                mma16816(oacc[ng * 2 + 1], ph, b1l);
                mma16816(oacc[ng * 2 + 1], pl, b1h);
            }
        }
        __syncthreads();
    }

    {
        int b = bh >> 3;
        int h2 = bh & 7;
        int ri = lane >> 2;
        int cc = (lane & 3) * 2;
        float li0 = 1.f / lsum[0];
        float li1 = 1.f / lsum[1];
        size_t t0 = (size_t)b * SS + q0 + warp * 16 + ri;
#pragma unroll
        for (int nf = 0; nf < 16; nf++) {
            int col = nf * 8 + cc;
            float2 o0 = make_float2(oacc[nf][0] * li0, oacc[nf][1] * li0);
            float2 o1 = make_float2(oacc[nf][2] * li1, oacc[nf][3] * li1);
            *(float2*)&g_res[t0 * 1024 + h2 * 128 + col] = o0;
            *(float2*)&g_res[(t0 + 8) * 1024 + h2 * 128 + col] = o1;
        }
    }
}

/* ------------------------------------------------------------------ */
extern "C" void kernel_launch(void* const* d_in, const int* in_sizes, int n_in,
                              void* d_out, int out_size) {
    (void)in_sizes; (void)n_in; (void)out_size;
    const float* q_src = (const float*)d_in[0];
    const float* k_src = (const float*)d_in[1];
    const float* v_src = (const float*)d_in[2];
    const float* Wq    = (const float*)d_in[3];
    const float* Wk    = (const float*)d_in[4];
    const float* Wv    = (const float*)d_in[5];
    const float* Wo    = (const float*)d_in[6];
    const float* sel_v = (const float*)d_in[7];
    const float* sel_o = (const float*)d_in[8];
    float* out = (float*)d_out;

    cudaFuncSetAttribute(attn_fa, cudaFuncAttributeMaxDynamicSharedMemorySize, ATTN_BYTES);
    cudaFuncSetAttribute(tc_gemm<0>, cudaFuncAttributeMaxDynamicSharedMemorySize, GCfg<0>::SMB);
    cudaFuncSetAttribute(tc_gemm<1>, cudaFuncAttributeMaxDynamicSharedMemorySize, GCfg<1>::SMB);
    cudaFuncSetAttribute(tc_gemm<2>, cudaFuncAttributeMaxDynamicSharedMemorySize, GCfg<2>::SMB);
    cudaFuncSetAttribute(tc_gemm<3>, cudaFuncAttributeMaxDynamicSharedMemorySize, GCfg<3>::SMB);

    wsplit<0><<<(DD * DD / 4 + 255) / 256, 256>>>((const float4*)Wq, DD * DD / 4);
    wsplit<1><<<(DD * DD / 4 + 255) / 256, 256>>>((const float4*)Wk, DD * DD / 4);
    wsplit<2><<<(HH * EE * DD * DHH / 4 + 255) / 256, 256>>>((const float4*)Wv, HH * EE * DD * DHH / 4);
    wsplit<3><<<(HH * EE * DHH * DD / 4 + 255) / 256, 256>>>((const float4*)Wo, HH * EE * DHH * DD / 4);
    gates_kernel<<<dim3(TOK / 8, 2), 256>>>(k_src, sel_v, q_src, sel_o);

    tc_gemm<0><<<dim3(8, 32), 256, GCfg<0>::SMB>>>(q_src, nullptr);
    tc_gemm<1><<<dim3(8, 32), 256, GCfg<1>::SMB>>>(k_src, nullptr);
    tc_gemm<2><<<dim3(1, 32, 8), 256, GCfg<2>::SMB>>>(v_src, nullptr);
    attn_fa<<<dim3(SS / 128, BB * HH), 256, ATTN_BYTES>>>();
    tc_gemm<3><<<dim3(8, 32), 256, GCfg<3>::SMB>>>(nullptr, out);
}

// round 14
// speedup vs baseline: 1.2197x; 1.1149x over previous
#include <cuda_runtime.h>
#include <cuda_bf16.h>
#include <cstdint>
#include <math.h>

#define BB   2
#define SS   2048
#define DD   1024
#define HH   8
#define EE   4
#define DHH  128
#define TOK  (BB*SS)
#define SCALE 0.29730177875068026f      /* 128^-0.25 */

/* ------------------------------------------------------------------ */
/* scratch (device globals)                                            */
/* ------------------------------------------------------------------ */
__device__ float g_res[TOK * DD];
__device__ float g_gv[TOK * HH * EE];
__device__ float g_go[TOK * HH * EE];

__device__ __nv_bfloat16 g_qh[TOK * DD], g_ql[TOK * DD];
__device__ __nv_bfloat16 g_kh[TOK * DD], g_kl[TOK * DD];
__device__ __nv_bfloat16 g_vh[TOK * DD], g_vl[TOK * DD];

__device__ __nv_bfloat16 g_wqh[DD * DD], g_wql[DD * DD];
__device__ __nv_bfloat16 g_wkh[DD * DD], g_wkl[DD * DD];
__device__ __nv_bfloat16 g_wvh[HH * EE * DD * DHH], g_wvl[HH * EE * DD * DHH];
__device__ __nv_bfloat16 g_woh[HH * EE * DHH * DD], g_wol[HH * EE * DHH * DD];

/* ------------------------------------------------------------------ */
/* helpers                                                             */
/* ------------------------------------------------------------------ */
__device__ __forceinline__ uint32_t smem_u32(const void* p) {
    return (uint32_t)__cvta_generic_to_shared(p);
}
__device__ __forceinline__ void ldsm4(uint32_t* r, uint32_t a) {
    asm volatile("ldmatrix.sync.aligned.m8n8.x4.shared.b16 {%0,%1,%2,%3}, [%4];"
                 : "=r"(r[0]), "=r"(r[1]), "=r"(r[2]), "=r"(r[3]) : "r"(a));
}
__device__ __forceinline__ void ldsm4t(uint32_t* r, uint32_t a) {
    asm volatile("ldmatrix.sync.aligned.m8n8.x4.trans.shared.b16 {%0,%1,%2,%3}, [%4];"
                 : "=r"(r[0]), "=r"(r[1]), "=r"(r[2]), "=r"(r[3]) : "r"(a));
}
__device__ __forceinline__ void mma16816(float* d, const uint32_t* a, const uint32_t* b) {
    asm volatile(
        "mma.sync.aligned.m16n8k16.row.col.f32.bf16.bf16.f32 "
        "{%0,%1,%2,%3}, {%4,%5,%6,%7}, {%8,%9}, {%0,%1,%2,%3};"
        : "+f"(d[0]), "+f"(d[1]), "+f"(d[2]), "+f"(d[3])
        : "r"(a[0]), "r"(a[1]), "r"(a[2]), "r"(a[3]), "r"(b[0]), "r"(b[1]));
}
__device__ __forceinline__ uint32_t packbf(float x, float y) {
    __nv_bfloat162 t = __floats2bfloat162_rn(x, y);
    return *reinterpret_cast<uint32_t*>(&t);
}
__device__ __forceinline__ void split_pair(float x, float y, uint32_t& h, uint32_t& l) {
    float hx = __bfloat162float(__float2bfloat16(x));
    float hy = __bfloat162float(__float2bfloat16(y));
    h = packbf(hx, hy);
    l = packbf(x - hx, y - hy);
}
__device__ __forceinline__ void cpa16(uint32_t dst, const void* src) {
    asm volatile("cp.async.cg.shared.global [%0], [%1], 16;" :: "r"(dst), "l"(src));
}
#define CP_COMMIT() asm volatile("cp.async.commit_group;" ::: "memory")
#define CP_WAIT0()  asm volatile("cp.async.wait_group 0;" ::: "memory")
#define CP_WAIT1()  asm volatile("cp.async.wait_group 1;" ::: "memory")

/* ------------------------------------------------------------------ */
/* PREP: fused wsplit(0..3) + gates, flat grid                         */
/* blocks: w0 [0,1024) w1 [1024,2048) w2 [2048,6144) w3 [6144,10240)   */
/*         gates [10240,11264): 512 x-blocks * 2 sides                 */
/* ------------------------------------------------------------------ */
__device__ void wsplit_body(const float4* __restrict__ src, int n4, int i,
                            uint2* dh, uint2* dl) {
    if (i >= n4) return;
    float4 x = src[i];
    uint32_t h0, l0, h1, l1;
    split_pair(x.x, x.y, h0, l0);
    split_pair(x.z, x.w, h1, l1);
    dh[i] = make_uint2(h0, h1);
    dl[i] = make_uint2(l0, l1);
}

__device__ void gates_body(const float* __restrict__ x, const float* __restrict__ sel,
                           float* __restrict__ out, int xblk) {
    int w = threadIdx.x >> 5;
    int lane = threadIdx.x & 31;
    int t = xblk * 8 + w;

    const float4* xr = (const float4*)(x + (size_t)t * DD);
    const float4* sr = (const float4*)(sel + (size_t)lane * DD);
    float acc = 0.f;
#pragma unroll 8
    for (int i = 0; i < DD / 4; i++) {
        float4 a = xr[i], b = sr[i];
        acc += a.x * b.x + a.y * b.y + a.z * b.z + a.w * b.w;
    }
    float g = 1.f / (1.f + __expf(-acc));

    __shared__ float sh[8][32];
    sh[w][lane] = g;
    __syncwarp();

    if (lane < HH) {
        float vv[4];
#pragma unroll
        for (int e = 0; e < 4; e++) vv[e] = sh[w][lane * 4 + e];
        int i1 = 0; float m1 = vv[0];
#pragma unroll
        for (int e = 1; e < 4; e++) if (vv[e] > m1) { m1 = vv[e]; i1 = e; }
        int i2 = -1; float m2 = -1e30f;
#pragma unroll
        for (int e = 0; e < 4; e++) if (e != i1 && vv[e] > m2) { m2 = vv[e]; i2 = e; }
#pragma unroll
        for (int e = 0; e < 4; e++)
            out[(size_t)t * 32 + lane * 4 + e] = (e == i1 || e == i2) ? vv[e] : 0.f;
    }
}

__global__ void __launch_bounds__(256)
prep_kernel(const float* __restrict__ q_src, const float* __restrict__ k_src,
            const float* __restrict__ Wq, const float* __restrict__ Wk,
            const float* __restrict__ Wv, const float* __restrict__ Wo,
            const float* __restrict__ sel_v, const float* __restrict__ sel_o) {
    int bid = blockIdx.x;
    if (bid < 1024) {
        wsplit_body((const float4*)Wq, DD * DD / 4, bid * 256 + threadIdx.x,
                    (uint2*)g_wqh, (uint2*)g_wql);
    } else if (bid < 2048) {
        wsplit_body((const float4*)Wk, DD * DD / 4, (bid - 1024) * 256 + threadIdx.x,
                    (uint2*)g_wkh, (uint2*)g_wkl);
    } else if (bid < 6144) {
        wsplit_body((const float4*)Wv, HH * EE * DD * DHH / 4,
                    (bid - 2048) * 256 + threadIdx.x, (uint2*)g_wvh, (uint2*)g_wvl);
    } else if (bid < 10240) {
        wsplit_body((const float4*)Wo, HH * EE * DHH * DD / 4,
                    (bid - 6144) * 256 + threadIdx.x, (uint2*)g_woh, (uint2*)g_wol);
    } else {
        int g = bid - 10240;          /* 0..1023: 512 xblk x 2 sides */
        int side = g >> 9, xblk = g & 511;
        if (side == 0) gates_body(k_src, sel_v, g_gv, xblk);
        else           gates_body(q_src, sel_o, g_go, xblk);
    }
}

/* ------------------------------------------------------------------ */
/* Tensor-core GEMM body (R8), block 128x128, Kc=32, split bf16.       */
/* ------------------------------------------------------------------ */
#define ASTR 40
#define BSTR 136

template <int MODE>
__device__ __forceinline__ void
tc_gemm_body(const float* __restrict__ A, float* __restrict__ C,
             int rowT, int colT, int hz,
             __nv_bfloat16* Ah, __nv_bfloat16* Al,
             __nv_bfloat16* Bh, __nv_bfloat16* Bl) {
    constexpr int KT = (MODE <= 1) ? 1024 : 4096;

    int tid = threadIdx.x;
    int warp = tid >> 5, lane = tid & 31;
    int wm = warp & 3, wn = warp >> 2;
    int row0 = rowT * 128;
    int col0 = colT * 128;

    const float* gates = (MODE == 2) ? g_gv : g_go;
    const __nv_bfloat16 *Bph, *Bpl;
    if (MODE == 0)      { Bph = g_wqh; Bpl = g_wql; }
    else if (MODE == 1) { Bph = g_wkh; Bpl = g_wkl; }
    else if (MODE == 2) { Bph = g_wvh + (size_t)hz * (EE * DD * DHH);
                          Bpl = g_wvl + (size_t)hz * (EE * DD * DHH); }
    else                { Bph = g_woh; Bpl = g_wol; }

    float d[2][8][4];
#pragma unroll
    for (int i = 0; i < 2; i++)
#pragma unroll
        for (int j = 0; j < 8; j++)
#pragma unroll
            for (int c = 0; c < 4; c++) d[i][j][c] = 0.f;

    for (int k0 = 0; k0 < KT; k0 += 32) {
#pragma unroll
        for (int it = 0; it < 4; it++) {
            int idx = it * 256 + tid;
            int r = idx >> 3, c4 = (idx & 7) * 4;
            int kg = k0 + c4;
            int rt = row0 + r;
            const float* src;
            float gm = 1.f;
            if (MODE <= 1) {
                src = A + (size_t)rt * 1024 + kg;
            } else if (MODE == 2) {
                src = A + (size_t)rt * 1024 + (kg & 1023);
                gm = gates[(size_t)rt * 32 + hz * 4 + (kg >> 10)];
            } else {
                int hh = kg >> 9, e = (kg >> 7) & 3, dh = kg & 127;
                src = g_res + (size_t)rt * 1024 + hh * 128 + dh;
                gm = gates[(size_t)rt * 32 + hh * 4 + e];
            }
            float4 x = *(const float4*)src;
            x.x *= gm; x.y *= gm; x.z *= gm; x.w *= gm;
            uint32_t h0, l0, h1, l1;
            split_pair(x.x, x.y, h0, l0);
            split_pair(x.z, x.w, h1, l1);
            *(uint32_t*)&Ah[r * ASTR + c4] = h0;
            *(uint32_t*)&Ah[r * ASTR + c4 + 2] = h1;
            *(uint32_t*)&Al[r * ASTR + c4] = l0;
            *(uint32_t*)&Al[r * ASTR + c4 + 2] = l1;
        }
        if (MODE <= 1) {
#pragma unroll
            for (int it = 0; it < 2; it++) {
                int idx = it * 256 + tid;
                int r = idx >> 2, c8 = (idx & 3) * 8;
                size_t so = (size_t)(col0 + r) * 1024 + k0 + c8;
                *(uint4*)&Bh[r * ASTR + c8] = *(const uint4*)(Bph + so);
                *(uint4*)&Bl[r * ASTR + c8] = *(const uint4*)(Bpl + so);
            }
        } else {
            constexpr int NLD = (MODE == 2) ? 128 : 1024;
#pragma unroll
            for (int it = 0; it < 2; it++) {
                int idx = it * 256 + tid;
                int kr = idx >> 4, c8 = (idx & 15) * 8;
                size_t so = (size_t)(k0 + kr) * NLD + col0 + c8;
                *(uint4*)&Bh[kr * BSTR + c8] = *(const uint4*)(Bph + so);
                *(uint4*)&Bl[kr * BSTR + c8] = *(const uint4*)(Bpl + so);
            }
        }
        __syncthreads();

#pragma unroll
        for (int ks = 0; ks < 2; ks++) {
            uint32_t ah[2][4], al[2][4];
#pragma unroll
            for (int mf = 0; mf < 2; mf++) {
                int off = (wm * 32 + mf * 16 + (lane & 15)) * ASTR + ks * 16 + (lane >> 4) * 8;
                ldsm4(ah[mf], smem_u32(&Ah[off]));
                ldsm4(al[mf], smem_u32(&Al[off]));
            }
            uint32_t bfh[16], bfl[16];
            if (MODE <= 1) {
#pragma unroll
                for (int nf2 = 0; nf2 < 4; nf2++) {
                    int off = (wn * 64 + nf2 * 16 + (lane & 15)) * ASTR + ks * 16 + (lane >> 4) * 8;
                    uint32_t r[4];
                    ldsm4(r, smem_u32(&Bh[off]));
                    bfh[nf2 * 4 + 0] = r[0]; bfh[nf2 * 4 + 1] = r[2];
                    bfh[nf2 * 4 + 2] = r[1]; bfh[nf2 * 4 + 3] = r[3];
                    ldsm4(r, smem_u32(&Bl[off]));
                    bfl[nf2 * 4 + 0] = r[0]; bfl[nf2 * 4 + 1] = r[2];
                    bfl[nf2 * 4 + 2] = r[1]; bfl[nf2 * 4 + 3] = r[3];
                }
            } else {
#pragma unroll
                for (int nf2 = 0; nf2 < 4; nf2++) {
                    int off = (ks * 16 + (lane & 15)) * BSTR + wn * 64 + nf2 * 16 + (lane >> 4) * 8;
                    uint32_t r[4];
                    ldsm4t(r, smem_u32(&Bh[off]));
                    bfh[nf2 * 4 + 0] = r[0]; bfh[nf2 * 4 + 1] = r[1];
                    bfh[nf2 * 4 + 2] = r[2]; bfh[nf2 * 4 + 3] = r[3];
                    ldsm4t(r, smem_u32(&Bl[off]));
                    bfl[nf2 * 4 + 0] = r[0]; bfl[nf2 * 4 + 1] = r[1];
                    bfl[nf2 * 4 + 2] = r[2]; bfl[nf2 * 4 + 3] = r[3];
                }
            }
#pragma unroll
            for (int mf = 0; mf < 2; mf++)
#pragma unroll
                for (int nf = 0; nf < 8; nf++) {
                    mma16816(d[mf][nf], ah[mf], &bfh[nf * 2]);
                    mma16816(d[mf][nf], ah[mf], &bfl[nf * 2]);
                    mma16816(d[mf][nf], al[mf], &bfh[nf * 2]);
                }
        }
        __syncthreads();
    }

    int ri = lane >> 2, c2 = (lane & 3) * 2;
#pragma unroll
    for (int mf = 0; mf < 2; mf++) {
#pragma unroll
        for (int nf = 0; nf < 8; nf++) {
            int col = col0 + wn * 64 + nf * 8 + c2;
#pragma unroll
            for (int hv = 0; hv < 2; hv++) {
                int row = row0 + wm * 32 + mf * 16 + ri + hv * 8;
                float v0 = d[mf][nf][hv * 2];
                float v1 = d[mf][nf][hv * 2 + 1];
                int bidx = row >> 11, sidx = row & 2047;
                if (MODE <= 1) {
                    v0 *= SCALE; v1 *= SCALE;
                    int hh = col >> 7, dh = col & 127;
                    size_t base = (((size_t)bidx * HH + hh) * SS + sidx) * DHH + dh;
                    uint32_t h, l;
                    split_pair(v0, v1, h, l);
                    __nv_bfloat16* dsth = (MODE == 0) ? g_qh : g_kh;
                    __nv_bfloat16* dstl = (MODE == 0) ? g_ql : g_kl;
                    *(uint32_t*)&dsth[base] = h;
                    *(uint32_t*)&dstl[base] = l;
                } else if (MODE == 2) {
                    size_t base = (((size_t)bidx * HH + hz) * SS + sidx) * DHH + col;
                    uint32_t h, l;
                    split_pair(v0, v1, h, l);
                    *(uint32_t*)&g_vh[base] = h;
                    *(uint32_t*)&g_vl[base] = l;
                } else {
                    float2 o = make_float2(v0, v1);
                    *(float2*)&C[(size_t)row * 1024 + col] = o;
                }
            }
        }
    }
}

/* fused m0+m1+m2: flat 768 blocks                                     */
__global__ void __launch_bounds__(256)
gemm012(const float* __restrict__ q_src, const float* __restrict__ k_src,
        const float* __restrict__ v_src) {
    __shared__ __nv_bfloat16 Ah[128 * ASTR];
    __shared__ __nv_bfloat16 Al[128 * ASTR];
    __shared__ __nv_bfloat16 Bh[128 * ASTR];
    __shared__ __nv_bfloat16 Bl[128 * ASTR];

    int bid = blockIdx.x;
    if (bid < 256) {
        tc_gemm_body<0>(q_src, nullptr, bid >> 3, bid & 7, 0, Ah, Al, Bh, Bl);
    } else if (bid < 512) {
        int lb = bid - 256;
        tc_gemm_body<1>(k_src, nullptr, lb >> 3, lb & 7, 0, Ah, Al, Bh, Bl);
    } else {
        int lb = bid - 512;            /* hz = lb>>5, rowT = lb&31, colT = 0 */
        tc_gemm_body<2>(v_src, nullptr, lb & 31, 0, lb >> 5, Ah, Al, Bh, Bl);
    }
}

/* m3 standalone */
__global__ void __launch_bounds__(256)
gemm3(float* __restrict__ C) {
    __shared__ __nv_bfloat16 Ah[128 * ASTR];
    __shared__ __nv_bfloat16 Al[128 * ASTR];
    __shared__ __nv_bfloat16 Bh[128 * ASTR];
    __shared__ __nv_bfloat16 Bl[128 * ASTR];
    tc_gemm_body<3>(nullptr, C, blockIdx.y, blockIdx.x, 0, Ah, Al, Bh, Bl);
}

/* ------------------------------------------------------------------ */
/* FA2 attention (R8): BQ=128, BKV=64, 8 warps, Q-frags in regs,       */
/* cp.async double-buffered K/V staging, register softmax.             */
/* ------------------------------------------------------------------ */
#define KVB  8704
#define BUFE (4 * KVB)
#define ATTN_BYTES (2 * BUFE * 2)

__device__ __forceinline__ void stage_kv(uint32_t smaddr, int bufe, int kv0, int tid,
                                         const __nv_bfloat16* kh, const __nv_bfloat16* kl,
                                         const __nv_bfloat16* vh, const __nv_bfloat16* vl) {
#pragma unroll
    for (int it = 0; it < 16; it++) {
        int idx = it * 256 + tid;
        int aid = idx >> 10;
        int rem = idx & 1023;
        int r = rem >> 4, c8 = (rem & 15) * 8;
        const __nv_bfloat16* s = (aid == 0) ? kh : (aid == 1) ? kl : (aid == 2) ? vh : vl;
        cpa16(smaddr + (uint32_t)(bufe + aid * KVB + r * 136 + c8) * 2,
              s + (size_t)(kv0 + r) * DHH + c8);
    }
}

__global__ void __launch_bounds__(256, 1) attn_fa() {
    extern __shared__ __nv_bfloat16 sm[];
    uint32_t smaddr = smem_u32(sm);

    int tid = threadIdx.x;
    int warp = tid >> 5, lane = tid & 31;
    int bh = blockIdx.y;
    int q0 = blockIdx.x * 128;

    const __nv_bfloat16* qh = g_qh + (size_t)bh * SS * DHH;
    const __nv_bfloat16* ql = g_ql + (size_t)bh * SS * DHH;
    const __nv_bfloat16* kh = g_kh + (size_t)bh * SS * DHH;
    const __nv_bfloat16* kl = g_kl + (size_t)bh * SS * DHH;
    const __nv_bfloat16* vh = g_vh + (size_t)bh * SS * DHH;
    const __nv_bfloat16* vl = g_vl + (size_t)bh * SS * DHH;

#pragma unroll
    for (int it = 0; it < 16; it++) {
        int idx = it * 256 + tid;
        int aid = idx >> 11;
        int rem = idx & 2047;
        int r = rem >> 4, c8 = (rem & 15) * 8;
        const __nv_bfloat16* s = aid ? ql : qh;
        cpa16(smaddr + (uint32_t)(aid * (128 * 136) + r * 136 + c8) * 2,
              s + (size_t)(q0 + r) * DHH + c8);
    }
    CP_COMMIT();
    CP_WAIT0();
    __syncthreads();

    uint32_t qfh[8][4], qfl[8][4];
#pragma unroll
    for (int ks = 0; ks < 8; ks++) {
        int off = (warp * 16 + (lane & 15)) * 136 + ks * 16 + (lane >> 4) * 8;
        ldsm4(qfh[ks], smaddr + (uint32_t)off * 2);
        ldsm4(qfl[ks], smaddr + (uint32_t)(128 * 136 + off) * 2);
    }
    __syncthreads();

    float oacc[16][4];
#pragma unroll
    for (int j = 0; j < 16; j++)
#pragma unroll
        for (int c = 0; c < 4; c++) oacc[j][c] = 0.f;
    float mold[2] = { -1e30f, -1e30f };
    float lsum[2] = { 0.f, 0.f };

    stage_kv(smaddr, 0, 0, tid, kh, kl, vh, vl);
    CP_COMMIT();

    for (int kvi = 0; kvi < SS / 64; kvi++) {
        int bufe = (kvi & 1) * BUFE;
        if (kvi + 1 < SS / 64)
            stage_kv(smaddr, ((kvi + 1) & 1) * BUFE, (kvi + 1) * 64, tid, kh, kl, vh, vl);
        CP_COMMIT();
        CP_WAIT1();
        __syncthreads();

        float sacc[8][4];
#pragma unroll
        for (int j = 0; j < 8; j++)
#pragma unroll
            for (int c = 0; c < 4; c++) sacc[j][c] = 0.f;

#pragma unroll
        for (int ks = 0; ks < 8; ks++) {
#pragma unroll
            for (int ng = 0; ng < 4; ng++) {
                int off = (ng * 16 + (lane & 15)) * 136 + ks * 16 + (lane >> 4) * 8;
                uint32_t rh[4], rl[4];
                ldsm4(rh, smaddr + (uint32_t)(bufe + off) * 2);
                ldsm4(rl, smaddr + (uint32_t)(bufe + KVB + off) * 2);
                uint32_t b0h[2] = { rh[0], rh[2] }, b1h[2] = { rh[1], rh[3] };
                uint32_t b0l[2] = { rl[0], rl[2] }, b1l[2] = { rl[1], rl[3] };
                mma16816(sacc[ng * 2], qfh[ks], b0h);
                mma16816(sacc[ng * 2], qfh[ks], b0l);
                mma16816(sacc[ng * 2], qfl[ks], b0h);
                mma16816(sacc[ng * 2 + 1], qfh[ks], b1h);
                mma16816(sacc[ng * 2 + 1], qfh[ks], b1l);
                mma16816(sacc[ng * 2 + 1], qfl[ks], b1h);
            }
        }

        float corr[2];
#pragma unroll
        for (int hf = 0; hf < 2; hf++) {
            float mx = -1e30f;
#pragma unroll
            for (int nf = 0; nf < 8; nf++) {
                mx = fmaxf(mx, sacc[nf][hf * 2]);
                mx = fmaxf(mx, sacc[nf][hf * 2 + 1]);
            }
            mx = fmaxf(mx, __shfl_xor_sync(0xffffffffu, mx, 1));
            mx = fmaxf(mx, __shfl_xor_sync(0xffffffffu, mx, 2));
            float mnew = fmaxf(mold[hf], mx);
            corr[hf] = __expf(mold[hf] - mnew);
            mold[hf] = mnew;
            float ls = 0.f;
#pragma unroll
            for (int nf = 0; nf < 8; nf++) {
                float p0 = __expf(sacc[nf][hf * 2] - mnew);
                float p1 = __expf(sacc[nf][hf * 2 + 1] - mnew);
                sacc[nf][hf * 2] = p0;
                sacc[nf][hf * 2 + 1] = p1;
                ls += p0 + p1;
            }
            ls += __shfl_xor_sync(0xffffffffu, ls, 1);
            ls += __shfl_xor_sync(0xffffffffu, ls, 2);
            lsum[hf] = lsum[hf] * corr[hf] + ls;
        }
#pragma unroll
        for (int nf = 0; nf < 16; nf++) {
            oacc[nf][0] *= corr[0]; oacc[nf][1] *= corr[0];
            oacc[nf][2] *= corr[1]; oacc[nf][3] *= corr[1];
        }

#pragma unroll
        for (int kk = 0; kk < 4; kk++) {
            uint32_t ph[4], pl[4];
            split_pair(sacc[kk * 2][0],     sacc[kk * 2][1],     ph[0], pl[0]);
            split_pair(sacc[kk * 2][2],     sacc[kk * 2][3],     ph[1], pl[1]);
            split_pair(sacc[kk * 2 + 1][0], sacc[kk * 2 + 1][1], ph[2], pl[2]);
            split_pair(sacc[kk * 2 + 1][2], sacc[kk * 2 + 1][3], ph[3], pl[3]);
#pragma unroll
            for (int ng = 0; ng < 8; ng++) {
                int off = (kk * 16 + (lane & 15)) * 136 + ng * 16 + (lane >> 4) * 8;
                uint32_t rh[4], rl[4];
                ldsm4t(rh, smaddr + (uint32_t)(bufe + 2 * KVB + off) * 2);
                ldsm4t(rl, smaddr + (uint32_t)(bufe + 3 * KVB + off) * 2);
                uint32_t b0h[2] = { rh[0], rh[1] }, b1h[2] = { rh[2], rh[3] };
                uint32_t b0l[2] = { rl[0], rl[1] }, b1l[2] = { rl[2], rl[3] };
                mma16816(oacc[ng * 2], ph, b0h);
                mma16816(oacc[ng * 2], ph, b0l);
                mma16816(oacc[ng * 2], pl, b0h);
                mma16816(oacc[ng * 2 + 1], ph, b1h);
                mma16816(oacc[ng * 2 + 1], ph, b1l);
                mma16816(oacc[ng * 2 + 1], pl, b1h);
            }
        }
        __syncthreads();
    }

    {
        int b = bh >> 3;
        int h2 = bh & 7;
        int ri = lane >> 2;
        int cc = (lane & 3) * 2;
        float li0 = 1.f / lsum[0];
        float li1 = 1.f / lsum[1];
        size_t t0 = (size_t)b * SS + q0 + warp * 16 + ri;
#pragma unroll
        for (int nf = 0; nf < 16; nf++) {
            int col = nf * 8 + cc;
            float2 o0 = make_float2(oacc[nf][0] * li0, oacc[nf][1] * li0);
            float2 o1 = make_float2(oacc[nf][2] * li1, oacc[nf][3] * li1);
            *(float2*)&g_res[t0 * 1024 + h2 * 128 + col] = o0;
            *(float2*)&g_res[(t0 + 8) * 1024 + h2 * 128 + col] = o1;
        }
    }
}

/* ------------------------------------------------------------------ */
extern "C" void kernel_launch(void* const* d_in, const int* in_sizes, int n_in,
                              void* d_out, int out_size) {
    (void)in_sizes; (void)n_in; (void)out_size;
    const float* q_src = (const float*)d_in[0];
    const float* k_src = (const float*)d_in[1];
    const float* v_src = (const float*)d_in[2];
    const float* Wq    = (const float*)d_in[3];
    const float* Wk    = (const float*)d_in[4];
    const float* Wv    = (const float*)d_in[5];
    const float* Wo    = (const float*)d_in[6];
    const float* sel_v = (const float*)d_in[7];
    const float* sel_o = (const float*)d_in[8];
    float* out = (float*)d_out;

    cudaFuncSetAttribute(attn_fa, cudaFuncAttributeMaxDynamicSharedMemorySize, ATTN_BYTES);

    prep_kernel<<<11264, 256>>>(q_src, k_src, Wq, Wk, Wv, Wo, sel_v, sel_o);
    gemm012<<<768, 256>>>(q_src, k_src, v_src);
    attn_fa<<<dim3(SS / 128, BB * HH), 256, ATTN_BYTES>>>();
    gemm3<<<dim3(8, 32), 256>>>(out);
}